// round 15
// baseline (speedup 1.0000x reference)
#include <cuda_runtime.h>
#include <cuda_fp16.h>
#include <math.h>
#include <stdint.h>

#define NTOK  3072
#define UNITS 1024
#define NHEAD 16
#define HDIM  64
#define NBLK  64

// fp16 operand pool: [x | Wq | Wk | Wv | Wo]
#define OFF_X  0
#define OFF_WQ (NTOK * UNITS)
#define OFF_WK (OFF_WQ + UNITS * UNITS)
#define OFF_WV (OFF_WK + UNITS * UNITS)
#define OFF_WO (OFF_WV + UNITS * UNITS)
#define H_TOT  (OFF_WO + UNITS * UNITS)

__device__ __align__(16) __half g_h[H_TOT];
__device__ __align__(16) __half g_QKVh[3 * NTOK * UNITS];
__device__ __align__(16) __half g_O[NTOK * UNITS];
__device__ int g_cnt[NBLK];
__device__ int g_off[NBLK];
__device__ int g_mem[NTOK];

__device__ __forceinline__ unsigned h2u(__half2 h) {
    return *reinterpret_cast<unsigned*>(&h);
}

// ---------------------------------------------------------------------------
// Prep: convert x + weights to fp16 once.
// ---------------------------------------------------------------------------
__global__ __launch_bounds__(256) void prep_kernel(
    const float* __restrict__ x,  const float* __restrict__ Wq,
    const float* __restrict__ Wk, const float* __restrict__ Wv,
    const float* __restrict__ Wo)
{
    int i = blockIdx.x * 256 + threadIdx.x;
    const float* src; int base;
    if      (i <  786432) { src = x;  base = 0;       }
    else if (i < 1048576) { src = Wq; base = 786432;  }
    else if (i < 1310720) { src = Wk; base = 1048576; }
    else if (i < 1572864) { src = Wv; base = 1310720; }
    else                  { src = Wo; base = 1572864; }
    float4 v = ((const float4*)src)[i - base];
    __half2 h0 = __floats2half2_rn(v.x, v.y);
    __half2 h1 = __floats2half2_rn(v.z, v.w);
    ((uint2*)g_h)[i] = make_uint2(h2u(h0), h2u(h1));
}

// ---------------------------------------------------------------------------
// Parallel index build: one warp per block id, order-preserving ballot ranks.
// ---------------------------------------------------------------------------
__global__ __launch_bounds__(32) void build_index_kernel(const int* __restrict__ ids) {
    int b    = blockIdx.x;
    int lane = threadIdx.x;
    int cnt = 0, off = 0;
    for (int i0 = 0; i0 < NTOK; i0 += 32) {
        int id = ids[i0 + lane];
        unsigned meq = __ballot_sync(0xFFFFFFFFu, id == b);
        unsigned mlt = __ballot_sync(0xFFFFFFFFu, id < b);
        cnt += __popc(meq);
        off += __popc(mlt);
    }
    if (lane == 0) { g_cnt[b] = cnt; g_off[b] = off; }
    int run = off;
    unsigned lmask = (1u << lane) - 1u;
    for (int i0 = 0; i0 < NTOK; i0 += 32) {
        int id = ids[i0 + lane];
        unsigned meq = __ballot_sync(0xFFFFFFFFu, id == b);
        if (id == b) g_mem[run + __popc(meq & lmask)] = i0 + lane;
        run += __popc(meq);
    }
}

// ---------------------------------------------------------------------------
// FP16 GEMM: CTA tile 128x256, warp tile 64x64, BK=32, 4-stage cp.async,
// ldmatrix + mma.m16n8k16. 256 threads = 8 warps (2x4). 1 CTA/SM.
// A stage: 128 rows x 80 B. B stage: 32 rows x 528 B ((k+c)%8 bank groups,
// conflict-free ldmatrix phases).
// ---------------------------------------------------------------------------
#define A_STR   80
#define B_STR   528
#define A_STG   (128 * A_STR)
#define B_STG   (32 * B_STR)
#define STG_B   (A_STG + B_STG)          // 27136
#define NSTG    4
#define DYNSMEM (NSTG * STG_B)           // 108544

__device__ __forceinline__ void cp16g(uint32_t dst, const void* src) {
    asm volatile("cp.async.cg.shared.global [%0], [%1], 16;" :: "r"(dst), "l"(src));
}
__device__ __forceinline__ void ldmA4(unsigned* f, uint32_t a) {
    asm volatile("ldmatrix.sync.aligned.m8n8.x4.shared.b16 {%0,%1,%2,%3}, [%4];"
                 : "=r"(f[0]), "=r"(f[1]), "=r"(f[2]), "=r"(f[3]) : "r"(a));
}
__device__ __forceinline__ void ldmB4t(unsigned* f, uint32_t a) {
    asm volatile("ldmatrix.sync.aligned.m8n8.x4.trans.shared.b16 {%0,%1,%2,%3}, [%4];"
                 : "=r"(f[0]), "=r"(f[1]), "=r"(f[2]), "=r"(f[3]) : "r"(a));
}
__device__ __forceinline__ void mma16816(float* c, const unsigned* a,
                                         unsigned b0, unsigned b1) {
    asm volatile(
        "mma.sync.aligned.m16n8k16.row.col.f32.f16.f16.f32 "
        "{%0,%1,%2,%3}, {%4,%5,%6,%7}, {%8,%9}, {%0,%1,%2,%3};"
        : "+f"(c[0]), "+f"(c[1]), "+f"(c[2]), "+f"(c[3])
        : "r"(a[0]), "r"(a[1]), "r"(a[2]), "r"(a[3]), "r"(b0), "r"(b1));
}

template <bool HOUT>
__device__ __forceinline__ void gemm_body(
    const __half* __restrict__ A, const __half* __restrict__ B,
    void* __restrict__ Cv, int NN, int K, int rowBase, int colBase)
{
    extern __shared__ __align__(16) char smem[];
    const uint32_t sb = (uint32_t)__cvta_generic_to_shared(smem);

    const int t    = threadIdx.x;
    const int lane = t & 31;
    const int warp = t >> 5;
    const int wr   = warp >> 2;
    const int wc   = warp & 3;
    const int r    = lane >> 2;
    const int cq   = lane & 3;

    // cp.async A: thread t -> row t>>1, two 16B chunks c = (t&1)*2 + {0,1}
    const int arow = t >> 1;
    const int ac0  = (t & 1) * 2;
    const __half* Ag = A + (size_t)(rowBase + arow) * K + ac0 * 8;
    const uint32_t adst = (uint32_t)(arow * A_STR + ac0 * 16);
    // cp.async B: thread t -> k-row t>>3, four chunks c = (t&7)*4 + {0..3}
    const int bkr = t >> 3;
    const int bc0 = (t & 7) * 4;
    const __half* Bg = B + (size_t)bkr * NN + colBase + bc0 * 8;
    const uint32_t bdst = (uint32_t)(A_STG + bkr * B_STR + bc0 * 16);

    const int sel = lane >> 3;
    const int lrw = lane & 7;
    uint32_t aoff[4];
#pragma unroll
    for (int i = 0; i < 4; i++) {
        int m0 = wr * 64 + i * 16 + (sel & 1) * 8 + lrw;
        aoff[i] = (uint32_t)(m0 * A_STR + (sel >> 1) * 16);
    }
    uint32_t boff[4];
#pragma unroll
    for (int jp = 0; jp < 4; jp++) {
        int krow = (sel & 1) * 8 + lrw;
        int n0 = wc * 64 + jp * 16 + (sel >> 1) * 8;
        boff[jp] = (uint32_t)(A_STG + krow * B_STR + n0 * 2);
    }

    float acc[4][8][4];
#pragma unroll
    for (int i = 0; i < 4; i++)
#pragma unroll
        for (int j = 0; j < 8; j++)
#pragma unroll
            for (int e = 0; e < 4; e++) acc[i][j][e] = 0.f;

    const int nT = K / 32;

    // prologue: tiles 0..2
#pragma unroll
    for (int pt = 0; pt < 3; pt++) {
        uint32_t st = sb + pt * STG_B;
        const int ko = pt * 32;
        cp16g(st + adst,      Ag + ko);
        cp16g(st + adst + 16, Ag + ko + 8);
#pragma unroll
        for (int c = 0; c < 4; c++)
            cp16g(st + bdst + c * 16, Bg + (size_t)ko * NN + c * 8);
        asm volatile("cp.async.commit_group;" ::: "memory");
    }

    for (int tt = 0; tt < nT; tt++) {
        asm volatile("cp.async.wait_group 2;" ::: "memory");
        __syncthreads();

        if (tt + 3 < nT) {
            uint32_t st = sb + ((tt + 3) % NSTG) * STG_B;
            const int ko = (tt + 3) * 32;
            cp16g(st + adst,      Ag + ko);
            cp16g(st + adst + 16, Ag + ko + 8);
#pragma unroll
            for (int c = 0; c < 4; c++)
                cp16g(st + bdst + c * 16, Bg + (size_t)ko * NN + c * 8);
        }
        asm volatile("cp.async.commit_group;" ::: "memory");

        const uint32_t st = sb + (tt % NSTG) * STG_B;
#pragma unroll
        for (int ks = 0; ks < 2; ks++) {
            unsigned af[4][4];
#pragma unroll
            for (int i = 0; i < 4; i++)
                ldmA4(af[i], st + aoff[i] + ks * 32);
            unsigned bf[8][2];
#pragma unroll
            for (int jp = 0; jp < 4; jp++) {
                unsigned bt[4];
                ldmB4t(bt, st + boff[jp] + ks * 16 * B_STR);
                bf[2 * jp + 0][0] = bt[0]; bf[2 * jp + 0][1] = bt[1];
                bf[2 * jp + 1][0] = bt[2]; bf[2 * jp + 1][1] = bt[3];
            }
#pragma unroll
            for (int i = 0; i < 4; i++)
#pragma unroll
                for (int j = 0; j < 8; j++)
                    mma16816(acc[i][j], af[i], bf[j][0], bf[j][1]);
        }
    }

#pragma unroll
    for (int i = 0; i < 4; i++) {
        int row0 = rowBase + wr * 64 + i * 16 + r;
#pragma unroll
        for (int j = 0; j < 8; j++) {
            int col = colBase + wc * 64 + j * 8 + 2 * cq;
            if (HOUT) {
                __half* C = (__half*)Cv;
                *(unsigned*)&C[(size_t)row0 * NN + col] =
                    h2u(__floats2half2_rn(acc[i][j][0], acc[i][j][1]));
                *(unsigned*)&C[(size_t)(row0 + 8) * NN + col] =
                    h2u(__floats2half2_rn(acc[i][j][2], acc[i][j][3]));
            } else {
                float* C = (float*)Cv;
                *(float2*)&C[(size_t)row0 * NN + col] =
                    make_float2(acc[i][j][0], acc[i][j][1]);
                *(float2*)&C[(size_t)(row0 + 8) * NN + col] =
                    make_float2(acc[i][j][2], acc[i][j][3]);
            }
        }
    }
}

__global__ __launch_bounds__(256, 1) void qkv_gemm() {
    const int z = blockIdx.z;
    gemm_body<true>(g_h + OFF_X, g_h + OFF_WQ + (size_t)z * UNITS * UNITS,
                    g_QKVh + (size_t)z * NTOK * UNITS, UNITS, UNITS,
                    blockIdx.y * 128, blockIdx.x * 256);
}
__global__ __launch_bounds__(256, 1) void out_gemm(float* __restrict__ out) {
    gemm_body<false>(g_O, g_h + OFF_WO, out, UNITS, UNITS,
                     blockIdx.y * 128, blockIdx.x * 256);
}

// ---------------------------------------------------------------------------
// Tensor-core flash attention (round-13 proven, unchanged).
// ---------------------------------------------------------------------------
#define QS_STR 72

__global__ __launch_bounds__(128) void attn_kernel(const float* __restrict__ mask) {
    int b = blockIdx.x;
    int h = blockIdx.y;
    int m = g_cnt[b];
    if (m == 0) return;
    int off = g_off[b];

    const __half* Qg = g_QKVh;
    const __half* Kg = g_QKVh + NTOK * UNITS;
    const __half* Vg = g_QKVh + 2 * NTOK * UNITS;

    __shared__ __align__(16) __half Qs[64 * QS_STR];
    __shared__ __align__(16) __half Ks[64 * QS_STR];
    __shared__ __align__(16) __half Vs[64 * QS_STR];
    __shared__ float bs[64];

    const int tid  = threadIdx.x;
    const int w    = tid >> 5;
    const int lane = tid & 31;
    const int gq   = lane >> 2;
    const int qq   = lane & 3;
    const int sel  = lane >> 3;
    const int lrw  = lane & 7;

    const uint32_t qsb = (uint32_t)__cvta_generic_to_shared(Qs);
    const uint32_t ksb = (uint32_t)__cvta_generic_to_shared(Ks);
    const uint32_t vsb = (uint32_t)__cvta_generic_to_shared(Vs);

    uint32_t qaddr[4];
#pragma unroll
    for (int ks = 0; ks < 4; ks++)
        qaddr[ks] = qsb + (uint32_t)(((16 * w + (sel & 1) * 8 + lrw) * QS_STR
                                      + (sel >> 1) * 8 + ks * 16) * 2);

    const int hb  = h * HDIM;
    const int nkt = (m + 63) >> 6;

    for (int q0 = 0; q0 < m; q0 += 64) {
        __syncthreads();
#pragma unroll
        for (int i = 0; i < 4; i++) {
            int id = i * 128 + tid;
            int row = id >> 3, ch = id & 7;
            int qi = q0 + row;
            int qt = (qi < m) ? g_mem[off + qi] : g_mem[off];
            uint4 v = *(const uint4*)(Qg + (size_t)qt * UNITS + hb + ch * 8);
            *(uint4*)(Qs + row * QS_STR + ch * 8) = v;
        }
        __syncthreads();

        unsigned qf[4][4];
#pragma unroll
        for (int ks = 0; ks < 4; ks++) ldmA4(qf[ks], qaddr[ks]);

        float oacc[8][4];
#pragma unroll
        for (int j = 0; j < 8; j++)
#pragma unroll
            for (int e = 0; e < 4; e++) oacc[j][e] = 0.f;
        float mxA = -3e38f, mxB = -3e38f, lA = 0.f, lB = 0.f;

        for (int kt = 0; kt < nkt; kt++) {
            int k0 = kt * 64;
            __syncthreads();
#pragma unroll
            for (int i = 0; i < 4; i++) {
                int id = i * 128 + tid;
                int row = id >> 3, ch = id & 7;
                int gk = k0 + row;
                uint4 kv, vv;
                if (gk < m) {
                    int tk = g_mem[off + gk];
                    kv = *(const uint4*)(Kg + (size_t)tk * UNITS + hb + ch * 8);
                    vv = *(const uint4*)(Vg + (size_t)tk * UNITS + hb + ch * 8);
                } else {
                    kv = vv = make_uint4(0, 0, 0, 0);
                }
                *(uint4*)(Ks + row * QS_STR + ch * 8) = kv;
                *(uint4*)(Vs + row * QS_STR + ch * 8) = vv;
            }
            if (tid < 64) {
                int gk = k0 + tid;
                bs[tid] = (gk < m) ? (1.0f - mask[g_mem[off + gk]]) * (-1e9f)
                                   : -2e9f;
            }
            __syncthreads();

            float sacc[8][4];
#pragma unroll
            for (int j = 0; j < 8; j++)
#pragma unroll
                for (int e = 0; e < 4; e++) sacc[j][e] = 0.f;
#pragma unroll
            for (int ks = 0; ks < 4; ks++) {
#pragma unroll
                for (int jp = 0; jp < 4; jp++) {
                    unsigned bt[4];
                    uint32_t ka = ksb + (uint32_t)(((jp * 16 + (sel >> 1) * 8 + lrw) * QS_STR
                                                   + ks * 16 + (sel & 1) * 8) * 2);
                    ldmA4(bt, ka);
                    mma16816(sacc[2 * jp + 0], qf[ks], bt[0], bt[1]);
                    mma16816(sacc[2 * jp + 1], qf[ks], bt[2], bt[3]);
                }
            }

            float s[8][4];
#pragma unroll
            for (int j = 0; j < 8; j++) {
                float2 bp = *(const float2*)&bs[j * 8 + 2 * qq];
                s[j][0] = sacc[j][0] * 0.125f + bp.x;
                s[j][1] = sacc[j][1] * 0.125f + bp.y;
                s[j][2] = sacc[j][2] * 0.125f + bp.x;
                s[j][3] = sacc[j][3] * 0.125f + bp.y;
            }
            float tA = -3e38f, tB = -3e38f;
#pragma unroll
            for (int j = 0; j < 8; j++) {
                tA = fmaxf(tA, fmaxf(s[j][0], s[j][1]));
                tB = fmaxf(tB, fmaxf(s[j][2], s[j][3]));
            }
            tA = fmaxf(tA, __shfl_xor_sync(0xFFFFFFFFu, tA, 1));
            tA = fmaxf(tA, __shfl_xor_sync(0xFFFFFFFFu, tA, 2));
            tB = fmaxf(tB, __shfl_xor_sync(0xFFFFFFFFu, tB, 1));
            tB = fmaxf(tB, __shfl_xor_sync(0xFFFFFFFFu, tB, 2));
            float nmA = fmaxf(mxA, tA), nmB = fmaxf(mxB, tB);
            float cA = __expf(mxA - nmA), cB = __expf(mxB - nmB);
            lA *= cA; lB *= cB;
#pragma unroll
            for (int j = 0; j < 8; j++) {
                oacc[j][0] *= cA; oacc[j][1] *= cA;
                oacc[j][2] *= cB; oacc[j][3] *= cB;
            }
            unsigned ph[8][2];
#pragma unroll
            for (int j = 0; j < 8; j++) {
                float p0 = __expf(s[j][0] - nmA);
                float p1 = __expf(s[j][1] - nmA);
                float p2 = __expf(s[j][2] - nmB);
                float p3 = __expf(s[j][3] - nmB);
                lA += p0 + p1; lB += p2 + p3;
                ph[j][0] = h2u(__floats2half2_rn(p0, p1));
                ph[j][1] = h2u(__floats2half2_rn(p2, p3));
            }
            mxA = nmA; mxB = nmB;

#pragma unroll
            for (int ks = 0; ks < 4; ks++) {
                unsigned af[4] = {ph[2 * ks][0], ph[2 * ks][1],
                                  ph[2 * ks + 1][0], ph[2 * ks + 1][1]};
#pragma unroll
                for (int jp = 0; jp < 4; jp++) {
                    unsigned bt[4];
                    uint32_t va = vsb + (uint32_t)(((ks * 16 + (sel & 1) * 8 + lrw) * QS_STR
                                                   + jp * 16 + (sel >> 1) * 8) * 2);
                    ldmB4t(bt, va);
                    mma16816(oacc[2 * jp + 0], af, bt[0], bt[1]);
                    mma16816(oacc[2 * jp + 1], af, bt[2], bt[3]);
                }
            }
        }

        lA += __shfl_xor_sync(0xFFFFFFFFu, lA, 1);
        lA += __shfl_xor_sync(0xFFFFFFFFu, lA, 2);
        lB += __shfl_xor_sync(0xFFFFFFFFu, lB, 1);
        lB += __shfl_xor_sync(0xFFFFFFFFu, lB, 2);
        float invA = 1.0f / lA, invB = 1.0f / lB;

        int rA = q0 + 16 * w + gq;
        int rB = rA + 8;
        if (rA < m) {
            __half* op = g_O + (size_t)g_mem[off + rA] * UNITS + hb;
#pragma unroll
            for (int j = 0; j < 8; j++)
                *(unsigned*)&op[j * 8 + 2 * qq] =
                    h2u(__floats2half2_rn(oacc[j][0] * invA, oacc[j][1] * invA));
        }
        if (rB < m) {
            __half* op = g_O + (size_t)g_mem[off + rB] * UNITS + hb;
#pragma unroll
            for (int j = 0; j < 8; j++)
                *(unsigned*)&op[j * 8 + 2 * qq] =
                    h2u(__floats2half2_rn(oacc[j][2] * invB, oacc[j][3] * invB));
        }
    }
}

// ---------------------------------------------------------------------------
extern "C" void kernel_launch(void* const* d_in, const int* in_sizes, int n_in,
                              void* d_out, int out_size)
{
    const float* x    = (const float*)d_in[0];
    const float* Wq   = (const float*)d_in[1];
    const float* Wk   = (const float*)d_in[2];
    const float* Wv   = (const float*)d_in[3];
    const float* Wo   = (const float*)d_in[4];
    const float* mask = (const float*)d_in[5];
    const int*   ids  = (const int*)d_in[6];
    float* out = (float*)d_out;

    cudaFuncSetAttribute(qkv_gemm,
        cudaFuncAttributeMaxDynamicSharedMemorySize, DYNSMEM);
    cudaFuncSetAttribute(out_gemm,
        cudaFuncAttributeMaxDynamicSharedMemorySize, DYNSMEM);

    prep_kernel<<<7168, 256>>>(x, Wq, Wk, Wv, Wo);
    build_index_kernel<<<NBLK, 32>>>(ids);

    dim3 gq(UNITS / 256, NTOK / 128, 3);
    qkv_gemm<<<gq, 256, DYNSMEM>>>();

    attn_kernel<<<dim3(NBLK, NHEAD), 128>>>(mask);

    dim3 go(UNITS / 256, NTOK / 128);
    out_gemm<<<go, 256, DYNSMEM>>>(out);
}

// round 16
// speedup vs baseline: 1.0546x; 1.0546x over previous
#include <cuda_runtime.h>
#include <cuda_fp16.h>
#include <math.h>
#include <stdint.h>

#define NTOK  3072
#define UNITS 1024
#define NHEAD 16
#define HDIM  64
#define NBLK  64

// fp16 operand pool: [x | Wq | Wk | Wv | Wo]
#define OFF_X  0
#define OFF_WQ (NTOK * UNITS)
#define OFF_WK (OFF_WQ + UNITS * UNITS)
#define OFF_WV (OFF_WK + UNITS * UNITS)
#define OFF_WO (OFF_WV + UNITS * UNITS)
#define H_TOT  (OFF_WO + UNITS * UNITS)

__device__ __align__(16) __half g_h[H_TOT];
__device__ __align__(16) __half g_QKVh[3 * NTOK * UNITS];
__device__ __align__(16) __half g_O[NTOK * UNITS];
__device__ int g_cnt[NBLK];
__device__ int g_off[NBLK];
__device__ int g_mem[NTOK];

__device__ __forceinline__ unsigned h2u(__half2 h) {
    return *reinterpret_cast<unsigned*>(&h);
}

// ---------------------------------------------------------------------------
// Prep: convert x + weights to fp16 once.
// ---------------------------------------------------------------------------
__global__ __launch_bounds__(256) void prep_kernel(
    const float* __restrict__ x,  const float* __restrict__ Wq,
    const float* __restrict__ Wk, const float* __restrict__ Wv,
    const float* __restrict__ Wo)
{
    int i = blockIdx.x * 256 + threadIdx.x;
    const float* src; int base;
    if      (i <  786432) { src = x;  base = 0;       }
    else if (i < 1048576) { src = Wq; base = 786432;  }
    else if (i < 1310720) { src = Wk; base = 1048576; }
    else if (i < 1572864) { src = Wv; base = 1310720; }
    else                  { src = Wo; base = 1572864; }
    float4 v = ((const float4*)src)[i - base];
    __half2 h0 = __floats2half2_rn(v.x, v.y);
    __half2 h1 = __floats2half2_rn(v.z, v.w);
    ((uint2*)g_h)[i] = make_uint2(h2u(h0), h2u(h1));
}

// ---------------------------------------------------------------------------
// Parallel index build: one warp per block id, order-preserving ballot ranks.
// ---------------------------------------------------------------------------
__global__ __launch_bounds__(32) void build_index_kernel(const int* __restrict__ ids) {
    int b    = blockIdx.x;
    int lane = threadIdx.x;
    int cnt = 0, off = 0;
    for (int i0 = 0; i0 < NTOK; i0 += 32) {
        int id = ids[i0 + lane];
        unsigned meq = __ballot_sync(0xFFFFFFFFu, id == b);
        unsigned mlt = __ballot_sync(0xFFFFFFFFu, id < b);
        cnt += __popc(meq);
        off += __popc(mlt);
    }
    if (lane == 0) { g_cnt[b] = cnt; g_off[b] = off; }
    int run = off;
    unsigned lmask = (1u << lane) - 1u;
    for (int i0 = 0; i0 < NTOK; i0 += 32) {
        int id = ids[i0 + lane];
        unsigned meq = __ballot_sync(0xFFFFFFFFu, id == b);
        if (id == b) g_mem[run + __popc(meq & lmask)] = i0 + lane;
        run += __popc(meq);
    }
}

// ---------------------------------------------------------------------------
// FP16 GEMM, cp.async 5-stage + ldmatrix + mma.m16n8k16.
// CTA tile 128x128, warp tile 64x32, 2 CTA/SM (round-14 proven geometry).
// NSTG=5 with wait_group 3: 3 tiles in flight (~750+ cyc latency tolerance).
// ---------------------------------------------------------------------------
#define A_STR   80
#define B_STR   272
#define A_STG   (128 * A_STR)
#define B_STG   (32 * B_STR)
#define STG_B   (A_STG + B_STG)          // 18944
#define NSTG    5
#define DYNSMEM (NSTG * STG_B)           // 94720

__device__ __forceinline__ void cp16g(uint32_t dst, const void* src) {
    asm volatile("cp.async.cg.shared.global [%0], [%1], 16;" :: "r"(dst), "l"(src));
}
__device__ __forceinline__ void ldmA4(unsigned* f, uint32_t a) {
    asm volatile("ldmatrix.sync.aligned.m8n8.x4.shared.b16 {%0,%1,%2,%3}, [%4];"
                 : "=r"(f[0]), "=r"(f[1]), "=r"(f[2]), "=r"(f[3]) : "r"(a));
}
__device__ __forceinline__ void ldmB4t(unsigned* f, uint32_t a) {
    asm volatile("ldmatrix.sync.aligned.m8n8.x4.trans.shared.b16 {%0,%1,%2,%3}, [%4];"
                 : "=r"(f[0]), "=r"(f[1]), "=r"(f[2]), "=r"(f[3]) : "r"(a));
}
__device__ __forceinline__ void mma16816(float* c, const unsigned* a,
                                         unsigned b0, unsigned b1) {
    asm volatile(
        "mma.sync.aligned.m16n8k16.row.col.f32.f16.f16.f32 "
        "{%0,%1,%2,%3}, {%4,%5,%6,%7}, {%8,%9}, {%0,%1,%2,%3};"
        : "+f"(c[0]), "+f"(c[1]), "+f"(c[2]), "+f"(c[3])
        : "r"(a[0]), "r"(a[1]), "r"(a[2]), "r"(a[3]), "r"(b0), "r"(b1));
}

template <bool HOUT>
__device__ __forceinline__ void gemm_body(
    const __half* __restrict__ A, const __half* __restrict__ B,
    void* __restrict__ Cv, int NN, int K, int rowBase, int colBase)
{
    extern __shared__ __align__(16) char smem[];
    const uint32_t sb = (uint32_t)__cvta_generic_to_shared(smem);

    const int t    = threadIdx.x;
    const int lane = t & 31;
    const int warp = t >> 5;
    const int wr   = warp >> 2;
    const int wc   = warp & 3;
    const int r    = lane >> 2;
    const int cq   = lane & 3;

    const int arow = t >> 1;
    const int ac0  = (t & 1) * 2;
    const __half* Ag = A + (size_t)(rowBase + arow) * K + ac0 * 8;
    const uint32_t adst = (uint32_t)(arow * A_STR + ac0 * 16);
    const int bkr = t >> 3;
    const int bc0 = (t & 7) * 2;
    const __half* Bg = B + (size_t)bkr * NN + colBase + bc0 * 8;
    const uint32_t bdst = (uint32_t)(A_STG + bkr * B_STR + bc0 * 16);

    const int sel = lane >> 3;
    const int lrw = lane & 7;
    uint32_t aoff[4];
#pragma unroll
    for (int i = 0; i < 4; i++) {
        int m0 = wr * 64 + i * 16 + (sel & 1) * 8 + lrw;
        aoff[i] = (uint32_t)(m0 * A_STR + (sel >> 1) * 16);
    }
    uint32_t boff[2];
#pragma unroll
    for (int jp = 0; jp < 2; jp++) {
        int krow = (sel & 1) * 8 + lrw;
        int n0 = wc * 32 + jp * 16 + (sel >> 1) * 8;
        boff[jp] = (uint32_t)(A_STG + krow * B_STR + n0 * 2);
    }

    float acc[4][4][4];
#pragma unroll
    for (int i = 0; i < 4; i++)
#pragma unroll
        for (int j = 0; j < 4; j++)
#pragma unroll
            for (int e = 0; e < 4; e++) acc[i][j][e] = 0.f;

    const int nT = K / 32;

    // prologue: tiles 0..3 into stages 0..3
#pragma unroll
    for (int pt = 0; pt < 4; pt++) {
        uint32_t st = sb + pt * STG_B;
        const int ko = pt * 32;
        cp16g(st + adst,      Ag + ko);
        cp16g(st + adst + 16, Ag + ko + 8);
        cp16g(st + bdst,      Bg + (size_t)ko * NN);
        cp16g(st + bdst + 16, Bg + (size_t)ko * NN + 8);
        asm volatile("cp.async.commit_group;" ::: "memory");
    }

    for (int tt = 0; tt < nT; tt++) {
        asm volatile("cp.async.wait_group 3;" ::: "memory");
        __syncthreads();

        if (tt + 4 < nT) {
            uint32_t st = sb + ((tt + 4) % NSTG) * STG_B;
            const int ko = (tt + 4) * 32;
            cp16g(st + adst,      Ag + ko);
            cp16g(st + adst + 16, Ag + ko + 8);
            cp16g(st + bdst,      Bg + (size_t)ko * NN);
            cp16g(st + bdst + 16, Bg + (size_t)ko * NN + 8);
        }
        asm volatile("cp.async.commit_group;" ::: "memory");

        const uint32_t st = sb + (tt % NSTG) * STG_B;
#pragma unroll
        for (int ks = 0; ks < 2; ks++) {
            unsigned af[4][4];
#pragma unroll
            for (int i = 0; i < 4; i++)
                ldmA4(af[i], st + aoff[i] + ks * 32);
            unsigned bf[4][2];
#pragma unroll
            for (int jp = 0; jp < 2; jp++) {
                unsigned bt[4];
                ldmB4t(bt, st + boff[jp] + ks * 16 * B_STR);
                bf[2 * jp + 0][0] = bt[0]; bf[2 * jp + 0][1] = bt[1];
                bf[2 * jp + 1][0] = bt[2]; bf[2 * jp + 1][1] = bt[3];
            }
#pragma unroll
            for (int i = 0; i < 4; i++)
#pragma unroll
                for (int j = 0; j < 4; j++)
                    mma16816(acc[i][j], af[i], bf[j][0], bf[j][1]);
        }
    }

#pragma unroll
    for (int i = 0; i < 4; i++) {
        int row0 = rowBase + wr * 64 + i * 16 + r;
#pragma unroll
        for (int j = 0; j < 4; j++) {
            int col = colBase + wc * 32 + j * 8 + 2 * cq;
            if (HOUT) {
                __half* C = (__half*)Cv;
                *(unsigned*)&C[(size_t)row0 * NN + col] =
                    h2u(__floats2half2_rn(acc[i][j][0], acc[i][j][1]));
                *(unsigned*)&C[(size_t)(row0 + 8) * NN + col] =
                    h2u(__floats2half2_rn(acc[i][j][2], acc[i][j][3]));
            } else {
                float* C = (float*)Cv;
                *(float2*)&C[(size_t)row0 * NN + col] =
                    make_float2(acc[i][j][0], acc[i][j][1]);
                *(float2*)&C[(size_t)(row0 + 8) * NN + col] =
                    make_float2(acc[i][j][2], acc[i][j][3]);
            }
        }
    }
}

__global__ __launch_bounds__(256, 2) void qkv_gemm() {
    const int z = blockIdx.z;
    gemm_body<true>(g_h + OFF_X, g_h + OFF_WQ + (size_t)z * UNITS * UNITS,
                    g_QKVh + (size_t)z * NTOK * UNITS, UNITS, UNITS,
                    blockIdx.y * 128, blockIdx.x * 128);
}
__global__ __launch_bounds__(256, 2) void out_gemm(float* __restrict__ out) {
    gemm_body<false>(g_O, g_h + OFF_WO, out, UNITS, UNITS,
                     blockIdx.y * 128, blockIdx.x * 128);
}

// ---------------------------------------------------------------------------
// Tensor-core flash attention (round-13 proven, unchanged).
// ---------------------------------------------------------------------------
#define QS_STR 72

__global__ __launch_bounds__(128) void attn_kernel(const float* __restrict__ mask) {
    int b = blockIdx.x;
    int h = blockIdx.y;
    int m = g_cnt[b];
    if (m == 0) return;
    int off = g_off[b];

    const __half* Qg = g_QKVh;
    const __half* Kg = g_QKVh + NTOK * UNITS;
    const __half* Vg = g_QKVh + 2 * NTOK * UNITS;

    __shared__ __align__(16) __half Qs[64 * QS_STR];
    __shared__ __align__(16) __half Ks[64 * QS_STR];
    __shared__ __align__(16) __half Vs[64 * QS_STR];
    __shared__ float bs[64];

    const int tid  = threadIdx.x;
    const int w    = tid >> 5;
    const int lane = tid & 31;
    const int gq   = lane >> 2;
    const int qq   = lane & 3;
    const int sel  = lane >> 3;
    const int lrw  = lane & 7;

    const uint32_t qsb = (uint32_t)__cvta_generic_to_shared(Qs);
    const uint32_t ksb = (uint32_t)__cvta_generic_to_shared(Ks);
    const uint32_t vsb = (uint32_t)__cvta_generic_to_shared(Vs);

    uint32_t qaddr[4];
#pragma unroll
    for (int ks = 0; ks < 4; ks++)
        qaddr[ks] = qsb + (uint32_t)(((16 * w + (sel & 1) * 8 + lrw) * QS_STR
                                      + (sel >> 1) * 8 + ks * 16) * 2);

    const int hb  = h * HDIM;
    const int nkt = (m + 63) >> 6;

    for (int q0 = 0; q0 < m; q0 += 64) {
        __syncthreads();
#pragma unroll
        for (int i = 0; i < 4; i++) {
            int id = i * 128 + tid;
            int row = id >> 3, ch = id & 7;
            int qi = q0 + row;
            int qt = (qi < m) ? g_mem[off + qi] : g_mem[off];
            uint4 v = *(const uint4*)(Qg + (size_t)qt * UNITS + hb + ch * 8);
            *(uint4*)(Qs + row * QS_STR + ch * 8) = v;
        }
        __syncthreads();

        unsigned qf[4][4];
#pragma unroll
        for (int ks = 0; ks < 4; ks++) ldmA4(qf[ks], qaddr[ks]);

        float oacc[8][4];
#pragma unroll
        for (int j = 0; j < 8; j++)
#pragma unroll
            for (int e = 0; e < 4; e++) oacc[j][e] = 0.f;
        float mxA = -3e38f, mxB = -3e38f, lA = 0.f, lB = 0.f;

        for (int kt = 0; kt < nkt; kt++) {
            int k0 = kt * 64;
            __syncthreads();
#pragma unroll
            for (int i = 0; i < 4; i++) {
                int id = i * 128 + tid;
                int row = id >> 3, ch = id & 7;
                int gk = k0 + row;
                uint4 kv, vv;
                if (gk < m) {
                    int tk = g_mem[off + gk];
                    kv = *(const uint4*)(Kg + (size_t)tk * UNITS + hb + ch * 8);
                    vv = *(const uint4*)(Vg + (size_t)tk * UNITS + hb + ch * 8);
                } else {
                    kv = vv = make_uint4(0, 0, 0, 0);
                }
                *(uint4*)(Ks + row * QS_STR + ch * 8) = kv;
                *(uint4*)(Vs + row * QS_STR + ch * 8) = vv;
            }
            if (tid < 64) {
                int gk = k0 + tid;
                bs[tid] = (gk < m) ? (1.0f - mask[g_mem[off + gk]]) * (-1e9f)
                                   : -2e9f;
            }
            __syncthreads();

            float sacc[8][4];
#pragma unroll
            for (int j = 0; j < 8; j++)
#pragma unroll
                for (int e = 0; e < 4; e++) sacc[j][e] = 0.f;
#pragma unroll
            for (int ks = 0; ks < 4; ks++) {
#pragma unroll
                for (int jp = 0; jp < 4; jp++) {
                    unsigned bt[4];
                    uint32_t ka = ksb + (uint32_t)(((jp * 16 + (sel >> 1) * 8 + lrw) * QS_STR
                                                   + ks * 16 + (sel & 1) * 8) * 2);
                    ldmA4(bt, ka);
                    mma16816(sacc[2 * jp + 0], qf[ks], bt[0], bt[1]);
                    mma16816(sacc[2 * jp + 1], qf[ks], bt[2], bt[3]);
                }
            }

            float s[8][4];
#pragma unroll
            for (int j = 0; j < 8; j++) {
                float2 bp = *(const float2*)&bs[j * 8 + 2 * qq];
                s[j][0] = sacc[j][0] * 0.125f + bp.x;
                s[j][1] = sacc[j][1] * 0.125f + bp.y;
                s[j][2] = sacc[j][2] * 0.125f + bp.x;
                s[j][3] = sacc[j][3] * 0.125f + bp.y;
            }
            float tA = -3e38f, tB = -3e38f;
#pragma unroll
            for (int j = 0; j < 8; j++) {
                tA = fmaxf(tA, fmaxf(s[j][0], s[j][1]));
                tB = fmaxf(tB, fmaxf(s[j][2], s[j][3]));
            }
            tA = fmaxf(tA, __shfl_xor_sync(0xFFFFFFFFu, tA, 1));
            tA = fmaxf(tA, __shfl_xor_sync(0xFFFFFFFFu, tA, 2));
            tB = fmaxf(tB, __shfl_xor_sync(0xFFFFFFFFu, tB, 1));
            tB = fmaxf(tB, __shfl_xor_sync(0xFFFFFFFFu, tB, 2));
            float nmA = fmaxf(mxA, tA), nmB = fmaxf(mxB, tB);
            float cA = __expf(mxA - nmA), cB = __expf(mxB - nmB);
            lA *= cA; lB *= cB;
#pragma unroll
            for (int j = 0; j < 8; j++) {
                oacc[j][0] *= cA; oacc[j][1] *= cA;
                oacc[j][2] *= cB; oacc[j][3] *= cB;
            }
            unsigned ph[8][2];
#pragma unroll
            for (int j = 0; j < 8; j++) {
                float p0 = __expf(s[j][0] - nmA);
                float p1 = __expf(s[j][1] - nmA);
                float p2 = __expf(s[j][2] - nmB);
                float p3 = __expf(s[j][3] - nmB);
                lA += p0 + p1; lB += p2 + p3;
                ph[j][0] = h2u(__floats2half2_rn(p0, p1));
                ph[j][1] = h2u(__floats2half2_rn(p2, p3));
            }
            mxA = nmA; mxB = nmB;

#pragma unroll
            for (int ks = 0; ks < 4; ks++) {
                unsigned af[4] = {ph[2 * ks][0], ph[2 * ks][1],
                                  ph[2 * ks + 1][0], ph[2 * ks + 1][1]};
#pragma unroll
                for (int jp = 0; jp < 4; jp++) {
                    unsigned bt[4];
                    uint32_t va = vsb + (uint32_t)(((ks * 16 + (sel & 1) * 8 + lrw) * QS_STR
                                                   + jp * 16 + (sel >> 1) * 8) * 2);
                    ldmB4t(bt, va);
                    mma16816(oacc[2 * jp + 0], af, bt[0], bt[1]);
                    mma16816(oacc[2 * jp + 1], af, bt[2], bt[3]);
                }
            }
        }

        lA += __shfl_xor_sync(0xFFFFFFFFu, lA, 1);
        lA += __shfl_xor_sync(0xFFFFFFFFu, lA, 2);
        lB += __shfl_xor_sync(0xFFFFFFFFu, lB, 1);
        lB += __shfl_xor_sync(0xFFFFFFFFu, lB, 2);
        float invA = 1.0f / lA, invB = 1.0f / lB;

        int rA = q0 + 16 * w + gq;
        int rB = rA + 8;
        if (rA < m) {
            __half* op = g_O + (size_t)g_mem[off + rA] * UNITS + hb;
#pragma unroll
            for (int j = 0; j < 8; j++)
                *(unsigned*)&op[j * 8 + 2 * qq] =
                    h2u(__floats2half2_rn(oacc[j][0] * invA, oacc[j][1] * invA));
        }
        if (rB < m) {
            __half* op = g_O + (size_t)g_mem[off + rB] * UNITS + hb;
#pragma unroll
            for (int j = 0; j < 8; j++)
                *(unsigned*)&op[j * 8 + 2 * qq] =
                    h2u(__floats2half2_rn(oacc[j][2] * invB, oacc[j][3] * invB));
        }
    }
}

// ---------------------------------------------------------------------------
extern "C" void kernel_launch(void* const* d_in, const int* in_sizes, int n_in,
                              void* d_out, int out_size)
{
    const float* x    = (const float*)d_in[0];
    const float* Wq   = (const float*)d_in[1];
    const float* Wk   = (const float*)d_in[2];
    const float* Wv   = (const float*)d_in[3];
    const float* Wo   = (const float*)d_in[4];
    const float* mask = (const float*)d_in[5];
    const int*   ids  = (const int*)d_in[6];
    float* out = (float*)d_out;

    cudaFuncSetAttribute(qkv_gemm,
        cudaFuncAttributeMaxDynamicSharedMemorySize, DYNSMEM);
    cudaFuncSetAttribute(out_gemm,
        cudaFuncAttributeMaxDynamicSharedMemorySize, DYNSMEM);

    prep_kernel<<<7168, 256>>>(x, Wq, Wk, Wv, Wo);
    build_index_kernel<<<NBLK, 32>>>(ids);

    dim3 gq(UNITS / 128, NTOK / 128, 3);
    qkv_gemm<<<gq, 256, DYNSMEM>>>();

    attn_kernel<<<dim3(NBLK, NHEAD), 128>>>(mask);

    dim3 go(UNITS / 128, NTOK / 128);
    out_gemm<<<go, 256, DYNSMEM>>>(out);
}

// round 17
// speedup vs baseline: 1.1455x; 1.0862x over previous
#include <cuda_runtime.h>
#include <cuda_fp16.h>
#include <math.h>
#include <stdint.h>

#define NTOK  3072
#define UNITS 1024
#define NHEAD 16
#define HDIM  64
#define NBLK  64

// fp16 operand pool: [x | Wq | Wk | Wv | Wo]
#define OFF_X  0
#define OFF_WQ (NTOK * UNITS)
#define OFF_WK (OFF_WQ + UNITS * UNITS)
#define OFF_WV (OFF_WK + UNITS * UNITS)
#define OFF_WO (OFF_WV + UNITS * UNITS)
#define H_TOT  (OFF_WO + UNITS * UNITS)

__device__ __align__(16) __half g_h[H_TOT];
__device__ __align__(16) __half g_QKVh[3 * NTOK * UNITS];
__device__ __align__(16) __half g_O[NTOK * UNITS];
__device__ int g_cnt[NBLK];
__device__ int g_off[NBLK];
__device__ int g_mem[NTOK];

__device__ __forceinline__ unsigned h2u(__half2 h) {
    return *reinterpret_cast<unsigned*>(&h);
}

// ---------------------------------------------------------------------------
// Fused prep + index build. Blocks [0,7168): fp16 conversion of x + weights.
// Blocks [7168, 7232): per-block-id member lists via warp-ballot (warp 0 only).
// ---------------------------------------------------------------------------
__global__ __launch_bounds__(256) void prep_index_kernel(
    const float* __restrict__ x,  const float* __restrict__ Wq,
    const float* __restrict__ Wk, const float* __restrict__ Wv,
    const float* __restrict__ Wo, const int* __restrict__ ids)
{
    if (blockIdx.x < 7168) {
        int i = blockIdx.x * 256 + threadIdx.x;
        const float* src; int base;
        if      (i <  786432) { src = x;  base = 0;       }
        else if (i < 1048576) { src = Wq; base = 786432;  }
        else if (i < 1310720) { src = Wk; base = 1048576; }
        else if (i < 1572864) { src = Wv; base = 1310720; }
        else                  { src = Wo; base = 1572864; }
        float4 v = ((const float4*)src)[i - base];
        __half2 h0 = __floats2half2_rn(v.x, v.y);
        __half2 h1 = __floats2half2_rn(v.z, v.w);
        ((uint2*)g_h)[i] = make_uint2(h2u(h0), h2u(h1));
        return;
    }
    if (threadIdx.x >= 32) return;       // warp 0 only
    int b    = blockIdx.x - 7168;        // 0..63
    int lane = threadIdx.x;
    int cnt = 0, off = 0;
    for (int i0 = 0; i0 < NTOK; i0 += 32) {
        int id = ids[i0 + lane];
        unsigned meq = __ballot_sync(0xFFFFFFFFu, id == b);
        unsigned mlt = __ballot_sync(0xFFFFFFFFu, id < b);
        cnt += __popc(meq);
        off += __popc(mlt);
    }
    if (lane == 0) { g_cnt[b] = cnt; g_off[b] = off; }
    int run = off;
    unsigned lmask = (1u << lane) - 1u;
    for (int i0 = 0; i0 < NTOK; i0 += 32) {
        int id = ids[i0 + lane];
        unsigned meq = __ballot_sync(0xFFFFFFFFu, id == b);
        if (id == b) g_mem[run + __popc(meq & lmask)] = i0 + lane;
        run += __popc(meq);
    }
}

// ---------------------------------------------------------------------------
// FP16 GEMM, cp.async 4-stage + ldmatrix + mma.m16n8k16 (round-14 proven).
// ---------------------------------------------------------------------------
#define A_STR   80
#define B_STR   272
#define A_STG   (128 * A_STR)
#define B_STG   (32 * B_STR)
#define STG_B   (A_STG + B_STG)
#define NSTG    4
#define DYNSMEM (NSTG * STG_B)

__device__ __forceinline__ void cp16g(uint32_t dst, const void* src) {
    asm volatile("cp.async.cg.shared.global [%0], [%1], 16;" :: "r"(dst), "l"(src));
}
__device__ __forceinline__ void ldmA4(unsigned* f, uint32_t a) {
    asm volatile("ldmatrix.sync.aligned.m8n8.x4.shared.b16 {%0,%1,%2,%3}, [%4];"
                 : "=r"(f[0]), "=r"(f[1]), "=r"(f[2]), "=r"(f[3]) : "r"(a));
}
__device__ __forceinline__ void ldmB4t(unsigned* f, uint32_t a) {
    asm volatile("ldmatrix.sync.aligned.m8n8.x4.trans.shared.b16 {%0,%1,%2,%3}, [%4];"
                 : "=r"(f[0]), "=r"(f[1]), "=r"(f[2]), "=r"(f[3]) : "r"(a));
}
__device__ __forceinline__ void mma16816(float* c, const unsigned* a,
                                         unsigned b0, unsigned b1) {
    asm volatile(
        "mma.sync.aligned.m16n8k16.row.col.f32.f16.f16.f32 "
        "{%0,%1,%2,%3}, {%4,%5,%6,%7}, {%8,%9}, {%0,%1,%2,%3};"
        : "+f"(c[0]), "+f"(c[1]), "+f"(c[2]), "+f"(c[3])
        : "r"(a[0]), "r"(a[1]), "r"(a[2]), "r"(a[3]), "r"(b0), "r"(b1));
}

template <bool HOUT>
__device__ __forceinline__ void gemm_body(
    const __half* __restrict__ A, const __half* __restrict__ B,
    void* __restrict__ Cv, int NN, int K, int rowBase, int colBase)
{
    extern __shared__ __align__(16) char smem[];
    const uint32_t sb = (uint32_t)__cvta_generic_to_shared(smem);

    const int t    = threadIdx.x;
    const int lane = t & 31;
    const int warp = t >> 5;
    const int wr   = warp >> 2;
    const int wc   = warp & 3;
    const int r    = lane >> 2;
    const int cq   = lane & 3;

    const int arow = t >> 1;
    const int ac0  = (t & 1) * 2;
    const __half* Ag = A + (size_t)(rowBase + arow) * K + ac0 * 8;
    const uint32_t adst = (uint32_t)(arow * A_STR + ac0 * 16);
    const int bkr = t >> 3;
    const int bc0 = (t & 7) * 2;
    const __half* Bg = B + (size_t)bkr * NN + colBase + bc0 * 8;
    const uint32_t bdst = (uint32_t)(A_STG + bkr * B_STR + bc0 * 16);

    const int sel = lane >> 3;
    const int lrw = lane & 7;
    uint32_t aoff[4];
#pragma unroll
    for (int i = 0; i < 4; i++) {
        int m0 = wr * 64 + i * 16 + (sel & 1) * 8 + lrw;
        aoff[i] = (uint32_t)(m0 * A_STR + (sel >> 1) * 16);
    }
    uint32_t boff[2];
#pragma unroll
    for (int jp = 0; jp < 2; jp++) {
        int krow = (sel & 1) * 8 + lrw;
        int n0 = wc * 32 + jp * 16 + (sel >> 1) * 8;
        boff[jp] = (uint32_t)(A_STG + krow * B_STR + n0 * 2);
    }

    float acc[4][4][4];
#pragma unroll
    for (int i = 0; i < 4; i++)
#pragma unroll
        for (int j = 0; j < 4; j++)
#pragma unroll
            for (int e = 0; e < 4; e++) acc[i][j][e] = 0.f;

    const int nT = K / 32;

#pragma unroll
    for (int pt = 0; pt < 3; pt++) {
        uint32_t st = sb + pt * STG_B;
        const int ko = pt * 32;
        cp16g(st + adst,      Ag + ko);
        cp16g(st + adst + 16, Ag + ko + 8);
        cp16g(st + bdst,      Bg + (size_t)ko * NN);
        cp16g(st + bdst + 16, Bg + (size_t)ko * NN + 8);
        asm volatile("cp.async.commit_group;" ::: "memory");
    }

    for (int tt = 0; tt < nT; tt++) {
        asm volatile("cp.async.wait_group 2;" ::: "memory");
        __syncthreads();

        if (tt + 3 < nT) {
            uint32_t st = sb + ((tt + 3) % NSTG) * STG_B;
            const int ko = (tt + 3) * 32;
            cp16g(st + adst,      Ag + ko);
            cp16g(st + adst + 16, Ag + ko + 8);
            cp16g(st + bdst,      Bg + (size_t)ko * NN);
            cp16g(st + bdst + 16, Bg + (size_t)ko * NN + 8);
        }
        asm volatile("cp.async.commit_group;" ::: "memory");

        const uint32_t st = sb + (tt % NSTG) * STG_B;
#pragma unroll
        for (int ks = 0; ks < 2; ks++) {
            unsigned af[4][4];
#pragma unroll
            for (int i = 0; i < 4; i++)
                ldmA4(af[i], st + aoff[i] + ks * 32);
            unsigned bf[4][2];
#pragma unroll
            for (int jp = 0; jp < 2; jp++) {
                unsigned bt[4];
                ldmB4t(bt, st + boff[jp] + ks * 16 * B_STR);
                bf[2 * jp + 0][0] = bt[0]; bf[2 * jp + 0][1] = bt[1];
                bf[2 * jp + 1][0] = bt[2]; bf[2 * jp + 1][1] = bt[3];
            }
#pragma unroll
            for (int i = 0; i < 4; i++)
#pragma unroll
                for (int j = 0; j < 4; j++)
                    mma16816(acc[i][j], af[i], bf[j][0], bf[j][1]);
        }
    }

#pragma unroll
    for (int i = 0; i < 4; i++) {
        int row0 = rowBase + wr * 64 + i * 16 + r;
#pragma unroll
        for (int j = 0; j < 4; j++) {
            int col = colBase + wc * 32 + j * 8 + 2 * cq;
            if (HOUT) {
                __half* C = (__half*)Cv;
                *(unsigned*)&C[(size_t)row0 * NN + col] =
                    h2u(__floats2half2_rn(acc[i][j][0], acc[i][j][1]));
                *(unsigned*)&C[(size_t)(row0 + 8) * NN + col] =
                    h2u(__floats2half2_rn(acc[i][j][2], acc[i][j][3]));
            } else {
                float* C = (float*)Cv;
                *(float2*)&C[(size_t)row0 * NN + col] =
                    make_float2(acc[i][j][0], acc[i][j][1]);
                *(float2*)&C[(size_t)(row0 + 8) * NN + col] =
                    make_float2(acc[i][j][2], acc[i][j][3]);
            }
        }
    }
}

__global__ __launch_bounds__(256, 2) void qkv_gemm() {
    const int z = blockIdx.z;
    gemm_body<true>(g_h + OFF_X, g_h + OFF_WQ + (size_t)z * UNITS * UNITS,
                    g_QKVh + (size_t)z * NTOK * UNITS, UNITS, UNITS,
                    blockIdx.y * 128, blockIdx.x * 128);
}
__global__ __launch_bounds__(256, 2) void out_gemm(float* __restrict__ out) {
    gemm_body<false>(g_O, g_h + OFF_WO, out, UNITS, UNITS,
                     blockIdx.y * 128, blockIdx.x * 128);
}

// ---------------------------------------------------------------------------
// Tensor-core flash attention (round-13 core, softmax folded in place to
// cut ~32 live registers -> higher occupancy).
// ---------------------------------------------------------------------------
#define QS_STR 72

__global__ __launch_bounds__(128) void attn_kernel(const float* __restrict__ mask) {
    int b = blockIdx.x;
    int h = blockIdx.y;
    int m = g_cnt[b];
    if (m == 0) return;
    int off = g_off[b];

    const __half* Qg = g_QKVh;
    const __half* Kg = g_QKVh + NTOK * UNITS;
    const __half* Vg = g_QKVh + 2 * NTOK * UNITS;

    __shared__ __align__(16) __half Qs[64 * QS_STR];
    __shared__ __align__(16) __half Ks[64 * QS_STR];
    __shared__ __align__(16) __half Vs[64 * QS_STR];
    __shared__ float bs[64];

    const int tid  = threadIdx.x;
    const int w    = tid >> 5;
    const int lane = tid & 31;
    const int gq   = lane >> 2;
    const int qq   = lane & 3;
    const int sel  = lane >> 3;
    const int lrw  = lane & 7;

    const uint32_t qsb = (uint32_t)__cvta_generic_to_shared(Qs);
    const uint32_t ksb = (uint32_t)__cvta_generic_to_shared(Ks);
    const uint32_t vsb = (uint32_t)__cvta_generic_to_shared(Vs);

    uint32_t qaddr[4];
#pragma unroll
    for (int ks = 0; ks < 4; ks++)
        qaddr[ks] = qsb + (uint32_t)(((16 * w + (sel & 1) * 8 + lrw) * QS_STR
                                      + (sel >> 1) * 8 + ks * 16) * 2);

    const int hb  = h * HDIM;
    const int nkt = (m + 63) >> 6;

    for (int q0 = 0; q0 < m; q0 += 64) {
        __syncthreads();
#pragma unroll
        for (int i = 0; i < 4; i++) {
            int id = i * 128 + tid;
            int row = id >> 3, ch = id & 7;
            int qi = q0 + row;
            int qt = (qi < m) ? g_mem[off + qi] : g_mem[off];
            uint4 v = *(const uint4*)(Qg + (size_t)qt * UNITS + hb + ch * 8);
            *(uint4*)(Qs + row * QS_STR + ch * 8) = v;
        }
        __syncthreads();

        unsigned qf[4][4];
#pragma unroll
        for (int ks = 0; ks < 4; ks++) ldmA4(qf[ks], qaddr[ks]);

        float oacc[8][4];
#pragma unroll
        for (int j = 0; j < 8; j++)
#pragma unroll
            for (int e = 0; e < 4; e++) oacc[j][e] = 0.f;
        float mxA = -3e38f, mxB = -3e38f, lA = 0.f, lB = 0.f;

        for (int kt = 0; kt < nkt; kt++) {
            int k0 = kt * 64;
            __syncthreads();
#pragma unroll
            for (int i = 0; i < 4; i++) {
                int id = i * 128 + tid;
                int row = id >> 3, ch = id & 7;
                int gk = k0 + row;
                uint4 kv, vv;
                if (gk < m) {
                    int tk = g_mem[off + gk];
                    kv = *(const uint4*)(Kg + (size_t)tk * UNITS + hb + ch * 8);
                    vv = *(const uint4*)(Vg + (size_t)tk * UNITS + hb + ch * 8);
                } else {
                    kv = vv = make_uint4(0, 0, 0, 0);
                }
                *(uint4*)(Ks + row * QS_STR + ch * 8) = kv;
                *(uint4*)(Vs + row * QS_STR + ch * 8) = vv;
            }
            if (tid < 64) {
                int gk = k0 + tid;
                bs[tid] = (gk < m) ? (1.0f - mask[g_mem[off + gk]]) * (-1e9f)
                                   : -2e9f;
            }
            __syncthreads();

            float sacc[8][4];
#pragma unroll
            for (int j = 0; j < 8; j++)
#pragma unroll
                for (int e = 0; e < 4; e++) sacc[j][e] = 0.f;
#pragma unroll
            for (int ks = 0; ks < 4; ks++) {
#pragma unroll
                for (int jp = 0; jp < 4; jp++) {
                    unsigned bt[4];
                    uint32_t ka = ksb + (uint32_t)(((jp * 16 + (sel >> 1) * 8 + lrw) * QS_STR
                                                   + ks * 16 + (sel & 1) * 8) * 2);
                    ldmA4(bt, ka);
                    mma16816(sacc[2 * jp + 0], qf[ks], bt[0], bt[1]);
                    mma16816(sacc[2 * jp + 1], qf[ks], bt[2], bt[3]);
                }
            }

            // softmax folded in place (no extra s[][] array)
#pragma unroll
            for (int j = 0; j < 8; j++) {
                float2 bp = *(const float2*)&bs[j * 8 + 2 * qq];
                sacc[j][0] = sacc[j][0] * 0.125f + bp.x;
                sacc[j][1] = sacc[j][1] * 0.125f + bp.y;
                sacc[j][2] = sacc[j][2] * 0.125f + bp.x;
                sacc[j][3] = sacc[j][3] * 0.125f + bp.y;
            }
            float tA = -3e38f, tB = -3e38f;
#pragma unroll
            for (int j = 0; j < 8; j++) {
                tA = fmaxf(tA, fmaxf(sacc[j][0], sacc[j][1]));
                tB = fmaxf(tB, fmaxf(sacc[j][2], sacc[j][3]));
            }
            tA = fmaxf(tA, __shfl_xor_sync(0xFFFFFFFFu, tA, 1));
            tA = fmaxf(tA, __shfl_xor_sync(0xFFFFFFFFu, tA, 2));
            tB = fmaxf(tB, __shfl_xor_sync(0xFFFFFFFFu, tB, 1));
            tB = fmaxf(tB, __shfl_xor_sync(0xFFFFFFFFu, tB, 2));
            float nmA = fmaxf(mxA, tA), nmB = fmaxf(mxB, tB);
            float cA = __expf(mxA - nmA), cB = __expf(mxB - nmB);
            lA *= cA; lB *= cB;
#pragma unroll
            for (int j = 0; j < 8; j++) {
                oacc[j][0] *= cA; oacc[j][1] *= cA;
                oacc[j][2] *= cB; oacc[j][3] *= cB;
            }
            unsigned ph[8][2];
#pragma unroll
            for (int j = 0; j < 8; j++) {
                float p0 = __expf(sacc[j][0] - nmA);
                float p1 = __expf(sacc[j][1] - nmA);
                float p2 = __expf(sacc[j][2] - nmB);
                float p3 = __expf(sacc[j][3] - nmB);
                lA += p0 + p1; lB += p2 + p3;
                ph[j][0] = h2u(__floats2half2_rn(p0, p1));
                ph[j][1] = h2u(__floats2half2_rn(p2, p3));
            }
            mxA = nmA; mxB = nmB;

#pragma unroll
            for (int ks = 0; ks < 4; ks++) {
                unsigned af[4] = {ph[2 * ks][0], ph[2 * ks][1],
                                  ph[2 * ks + 1][0], ph[2 * ks + 1][1]};
#pragma unroll
                for (int jp = 0; jp < 4; jp++) {
                    unsigned bt[4];
                    uint32_t va = vsb + (uint32_t)(((ks * 16 + (sel & 1) * 8 + lrw) * QS_STR
                                                   + jp * 16 + (sel >> 1) * 8) * 2);
                    ldmB4t(bt, va);
                    mma16816(oacc[2 * jp + 0], af, bt[0], bt[1]);
                    mma16816(oacc[2 * jp + 1], af, bt[2], bt[3]);
                }
            }
        }

        lA += __shfl_xor_sync(0xFFFFFFFFu, lA, 1);
        lA += __shfl_xor_sync(0xFFFFFFFFu, lA, 2);
        lB += __shfl_xor_sync(0xFFFFFFFFu, lB, 1);
        lB += __shfl_xor_sync(0xFFFFFFFFu, lB, 2);
        float invA = 1.0f / lA, invB = 1.0f / lB;

        int rA = q0 + 16 * w + gq;
        int rB = rA + 8;
        if (rA < m) {
            __half* op = g_O + (size_t)g_mem[off + rA] * UNITS + hb;
#pragma unroll
            for (int j = 0; j < 8; j++)
                *(unsigned*)&op[j * 8 + 2 * qq] =
                    h2u(__floats2half2_rn(oacc[j][0] * invA, oacc[j][1] * invA));
        }
        if (rB < m) {
            __half* op = g_O + (size_t)g_mem[off + rB] * UNITS + hb;
#pragma unroll
            for (int j = 0; j < 8; j++)
                *(unsigned*)&op[j * 8 + 2 * qq] =
                    h2u(__floats2half2_rn(oacc[j][2] * invB, oacc[j][3] * invB));
        }
    }
}

// ---------------------------------------------------------------------------
extern "C" void kernel_launch(void* const* d_in, const int* in_sizes, int n_in,
                              void* d_out, int out_size)
{
    const float* x    = (const float*)d_in[0];
    const float* Wq   = (const float*)d_in[1];
    const float* Wk   = (const float*)d_in[2];
    const float* Wv   = (const float*)d_in[3];
    const float* Wo   = (const float*)d_in[4];
    const float* mask = (const float*)d_in[5];
    const int*   ids  = (const int*)d_in[6];
    float* out = (float*)d_out;

    cudaFuncSetAttribute(qkv_gemm,
        cudaFuncAttributeMaxDynamicSharedMemorySize, DYNSMEM);
    cudaFuncSetAttribute(out_gemm,
        cudaFuncAttributeMaxDynamicSharedMemorySize, DYNSMEM);

    prep_index_kernel<<<7168 + 64, 256>>>(x, Wq, Wk, Wv, Wo, ids);

    dim3 gq(UNITS / 128, NTOK / 128, 3);
    qkv_gemm<<<gq, 256, DYNSMEM>>>();

    attn_kernel<<<dim3(NBLK, NHEAD), 128>>>(mask);

    dim3 go(UNITS / 128, NTOK / 128);
    out_gemm<<<go, 256, DYNSMEM>>>(out);
}